// round 17
// baseline (speedup 1.0000x reference)
#include <cuda_runtime.h>
#include <cuda_bf16.h>
#include <mma.h>
#include <cstdint>
#include <cstddef>

using namespace nvcuda;

#define B_ 2
#define L_ 1920
#define D_ 512
#define H_ 8
#define DH_ 64
#define BH_ (B_*H_)
#define NT_ 30
#define OUT_ELEMS (B_*L_*D_)
#define NSPLIT 4
#define SPLITW 480

// Scratch (device globals; no cudaMalloc allowed)
__device__ float g_qp[B_*L_*D_];
__device__ float g_kp[B_*L_*D_];
__device__ float g_vp[B_*L_*D_];
__device__ float g_op[NSPLIT * BH_*L_*DH_];
__device__ float g_s[BH_*NT_*L_];          // per (bh,kt,q): tile row sum of exp
__device__ float g_I[BH_*L_];              // per row: 1/sum
// bf16 hi/lo splits
__device__ __nv_bfloat16 g_ih[3u*3840u*512u];
__device__ __nv_bfloat16 g_il[3u*3840u*512u];
__device__ __nv_bfloat16 g_wh[3u*512u*512u];
__device__ __nv_bfloat16 g_wl[3u*512u*512u];
__device__ __nv_bfloat16 g_qph[3840u*512u];   // qp/kp/vp hi/lo (for scores/av)
__device__ __nv_bfloat16 g_qpl[3840u*512u];
__device__ __nv_bfloat16 g_kph[3840u*512u];
__device__ __nv_bfloat16 g_kpl[3840u*512u];
__device__ __nv_bfloat16 g_vph[3840u*512u];
__device__ __nv_bfloat16 g_vpl[3840u*512u];
__device__ __nv_bfloat16 g_eh[1921u*512u];    // E hi/lo
__device__ __nv_bfloat16 g_el[1921u*512u];

// ---------------------------------------------------------------------------
// Split q/k/v inputs into bf16 hi/lo.
// ---------------------------------------------------------------------------
__global__ __launch_bounds__(256)
void split_in_kernel(const float* __restrict__ q, const float* __restrict__ k,
                     const float* __restrict__ v)
{
    int z = blockIdx.y;
    const float* src = (z == 0) ? q : (z == 1) ? k : v;
    size_t b4 = (size_t)blockIdx.x * 256 + threadIdx.x;
    float4 xv = ((const float4*)src)[b4];
    float xs[4] = {xv.x, xv.y, xv.z, xv.w};
    __nv_bfloat16 hb[4], lb[4];
    #pragma unroll
    for (int j = 0; j < 4; j++) {
        hb[j] = __float2bfloat16(xs[j]);
        lb[j] = __float2bfloat16(xs[j] - __bfloat162float(hb[j]));
    }
    size_t e0 = (size_t)z * (3840u*512u) + b4 * 4;
    __nv_bfloat162* dh = (__nv_bfloat162*)(g_ih + e0);
    __nv_bfloat162* dl = (__nv_bfloat162*)(g_il + e0);
    dh[0] = __halves2bfloat162(hb[0], hb[1]);
    dh[1] = __halves2bfloat162(hb[2], hb[3]);
    dl[0] = __halves2bfloat162(lb[0], lb[1]);
    dl[1] = __halves2bfloat162(lb[2], lb[3]);
}

// ---------------------------------------------------------------------------
// Split weights into bf16 hi/lo.
// ---------------------------------------------------------------------------
__global__ __launch_bounds__(256)
void split_w_kernel(const float* __restrict__ Wq, const float* __restrict__ Wk,
                    const float* __restrict__ Wv)
{
    int z = blockIdx.y;
    const float* W = (z == 0) ? Wq : (z == 1) ? Wk : Wv;
    size_t b4 = (size_t)blockIdx.x * 256 + threadIdx.x;
    float4 xv = ((const float4*)W)[b4];
    float xs[4] = {xv.x, xv.y, xv.z, xv.w};
    __nv_bfloat16 hb[4], lb[4];
    #pragma unroll
    for (int j = 0; j < 4; j++) {
        hb[j] = __float2bfloat16(xs[j]);
        lb[j] = __float2bfloat16(xs[j] - __bfloat162float(hb[j]));
    }
    size_t e0 = (size_t)z * (512u*512u) + b4 * 4;
    __nv_bfloat162* dh = (__nv_bfloat162*)(g_wh + e0);
    __nv_bfloat162* dl = (__nv_bfloat162*)(g_wl + e0);
    dh[0] = __halves2bfloat162(hb[0], hb[1]);
    dh[1] = __halves2bfloat162(hb[2], hb[3]);
    dl[0] = __halves2bfloat162(lb[0], lb[1]);
    dl[1] = __halves2bfloat162(lb[2], lb[3]);
}

// ---------------------------------------------------------------------------
// Split E into bf16 hi/lo (1921 x 512).
// ---------------------------------------------------------------------------
__global__ __launch_bounds__(256)
void split_e_kernel(const float* __restrict__ E)
{
    size_t b4 = (size_t)blockIdx.x * 256 + threadIdx.x;
    if (b4 * 4 >= 1921u*512u) return;
    float4 xv = ((const float4*)E)[b4];
    float xs[4] = {xv.x, xv.y, xv.z, xv.w};
    __nv_bfloat16 hb[4], lb[4];
    #pragma unroll
    for (int j = 0; j < 4; j++) {
        hb[j] = __float2bfloat16(xs[j]);
        lb[j] = __float2bfloat16(xs[j] - __bfloat162float(hb[j]));
    }
    __nv_bfloat162* dh = (__nv_bfloat162*)(g_eh + b4 * 4);
    __nv_bfloat162* dl = (__nv_bfloat162*)(g_el + b4 * 4);
    dh[0] = __halves2bfloat162(hb[0], hb[1]);
    dh[1] = __halves2bfloat162(hb[2], hb[3]);
    dl[0] = __halves2bfloat162(lb[0], lb[1]);
    dl[1] = __halves2bfloat162(lb[2], lb[3]);
}

// ---------------------------------------------------------------------------
// WMMA QKV GEMM (verified R13/R16). Emits bf16 hi/lo of qp/kp/vp.
// ---------------------------------------------------------------------------
#define ASTRIDE 40
#define BSTRIDE 72
#define AH_OFF 0
#define AL_OFF 10240
#define BHI_OFF 20480
#define BLO_OFF 25088
#define QKV_DSMEM (128*68*4)

__global__ __launch_bounds__(256)
void qkv_wmma_kernel(const float* __restrict__ bq, const float* __restrict__ bk,
                     const float* __restrict__ bv)
{
    extern __shared__ char dsm[];
    int tid = threadIdx.x, wid = tid >> 5;
    int z = blockIdx.z, m0 = blockIdx.y * 128, n0 = blockIdx.x * 64;

    const __nv_bfloat16* Ah = g_ih + (size_t)z * (3840u*512u);
    const __nv_bfloat16* Al = g_il + (size_t)z * (3840u*512u);
    const __nv_bfloat16* Bh = g_wh + (size_t)z * (512u*512u);
    const __nv_bfloat16* Bl = g_wl + (size_t)z * (512u*512u);
    float* C = (z == 0) ? g_qp : (z == 1) ? g_kp : g_vp;
    const float* bias = (z == 0) ? bq : (z == 1) ? bk : bv;

    __nv_bfloat16* sAh = (__nv_bfloat16*)(dsm + AH_OFF);
    __nv_bfloat16* sAl = (__nv_bfloat16*)(dsm + AL_OFF);
    __nv_bfloat16* sBh = (__nv_bfloat16*)(dsm + BHI_OFF);
    __nv_bfloat16* sBl = (__nv_bfloat16*)(dsm + BLO_OFF);

    int wm = wid & 3, wn = wid >> 2;

    wmma::fragment<wmma::accumulator, 16, 16, 16, float> acc[2][2];
    #pragma unroll
    for (int i = 0; i < 2; i++)
        #pragma unroll
        for (int j = 0; j < 2; j++)
            wmma::fill_fragment(acc[i][j], 0.0f);

    for (int k0 = 0; k0 < 512; k0 += 32) {
        #pragma unroll
        for (int t = 0; t < 2; t++) {
            int u = tid * 2 + t;
            int r = u >> 2, c4 = u & 3;
            *(uint4*)(sAh + r * ASTRIDE + c4 * 8) =
                *(const uint4*)(Ah + (size_t)(m0 + r) * 512 + k0 + c4 * 8);
            *(uint4*)(sAl + r * ASTRIDE + c4 * 8) =
                *(const uint4*)(Al + (size_t)(m0 + r) * 512 + k0 + c4 * 8);
        }
        {
            int r = tid >> 3, c4 = tid & 7;
            *(uint4*)(sBh + r * BSTRIDE + c4 * 8) =
                *(const uint4*)(Bh + (size_t)(k0 + r) * 512 + n0 + c4 * 8);
            *(uint4*)(sBl + r * BSTRIDE + c4 * 8) =
                *(const uint4*)(Bl + (size_t)(k0 + r) * 512 + n0 + c4 * 8);
        }
        __syncthreads();

        #pragma unroll
        for (int kk = 0; kk < 32; kk += 16) {
            wmma::fragment<wmma::matrix_a, 16, 16, 16, __nv_bfloat16, wmma::row_major> ah[2], al[2];
            wmma::fragment<wmma::matrix_b, 16, 16, 16, __nv_bfloat16, wmma::row_major> bh[2], bl[2];
            #pragma unroll
            for (int i = 0; i < 2; i++) {
                wmma::load_matrix_sync(ah[i], sAh + (wm*32 + i*16) * ASTRIDE + kk, ASTRIDE);
                wmma::load_matrix_sync(al[i], sAl + (wm*32 + i*16) * ASTRIDE + kk, ASTRIDE);
            }
            #pragma unroll
            for (int j = 0; j < 2; j++) {
                wmma::load_matrix_sync(bh[j], sBh + kk * BSTRIDE + wn*32 + j*16, BSTRIDE);
                wmma::load_matrix_sync(bl[j], sBl + kk * BSTRIDE + wn*32 + j*16, BSTRIDE);
            }
            #pragma unroll
            for (int i = 0; i < 2; i++)
                #pragma unroll
                for (int j = 0; j < 2; j++) {
                    wmma::mma_sync(acc[i][j], ah[i], bh[j], acc[i][j]);
                    wmma::mma_sync(acc[i][j], ah[i], bl[j], acc[i][j]);
                    wmma::mma_sync(acc[i][j], al[i], bh[j], acc[i][j]);
                }
        }
        __syncthreads();
    }

    float* Cs = (float*)dsm;
    #pragma unroll
    for (int i = 0; i < 2; i++)
        #pragma unroll
        for (int j = 0; j < 2; j++)
            wmma::store_matrix_sync(Cs + (size_t)(wm*32 + i*16) * 68 + wn*32 + j*16,
                                    acc[i][j], 68, wmma::mem_row_major);
    __syncthreads();

    #pragma unroll
    for (int t = 0; t < 8; t++) {
        int u = tid + t * 256;
        int r = u >> 4, c4 = u & 15;
        float4 o = *(float4*)(Cs + (size_t)r * 68 + c4 * 4);
        o.x += bias[n0 + c4*4 + 0]; o.y += bias[n0 + c4*4 + 1];
        o.z += bias[n0 + c4*4 + 2]; o.w += bias[n0 + c4*4 + 3];
        size_t base = (size_t)(m0 + r) * 512 + n0 + c4 * 4;
        *(float4*)(C + base) = o;
        {   // bf16 hi/lo for scores/av consumption
            __nv_bfloat16* Hh = (z == 0) ? g_qph : (z == 1) ? g_kph : g_vph;
            __nv_bfloat16* Hl = (z == 0) ? g_qpl : (z == 1) ? g_kpl : g_vpl;
            float os[4] = {o.x, o.y, o.z, o.w};
            __nv_bfloat16 hb[4], lb[4];
            #pragma unroll
            for (int j = 0; j < 4; j++) {
                hb[j] = __float2bfloat16(os[j]);
                lb[j] = __float2bfloat16(os[j] - __bfloat162float(hb[j]));
            }
            __nv_bfloat162* dh = (__nv_bfloat162*)(Hh + base);
            __nv_bfloat162* dl = (__nv_bfloat162*)(Hl + base);
            dh[0] = __halves2bfloat162(hb[0], hb[1]);
            dh[1] = __halves2bfloat162(hb[2], hb[3]);
            dl[0] = __halves2bfloat162(lb[0], lb[1]);
            dl[1] = __halves2bfloat162(lb[2], lb[3]);
        }
    }
}

// ---------------------------------------------------------------------------
// WMMA scores (verified R16): S = Q@K^T, T = Q@Eband^T, ex = exp masked.
// ---------------------------------------------------------------------------
#define SQH 0
#define SQL 9216
#define SKH 18432
#define SKL 27648
#define SEH 36864
#define SEL 55296
#define SCW_SMEM 73728

__global__ __launch_bounds__(256)
void scores_wmma_kernel(float* __restrict__ attn)
{
    extern __shared__ char dsm[];
    __nv_bfloat16* sQh = (__nv_bfloat16*)(dsm + SQH);
    __nv_bfloat16* sQl = (__nv_bfloat16*)(dsm + SQL);
    __nv_bfloat16* sKh = (__nv_bfloat16*)(dsm + SKH);
    __nv_bfloat16* sKl = (__nv_bfloat16*)(dsm + SKL);
    __nv_bfloat16* sEh = (__nv_bfloat16*)(dsm + SEH);
    __nv_bfloat16* sEl = (__nv_bfloat16*)(dsm + SEL);
    float* SO = (float*)dsm;
    float* TO = (float*)dsm + 64*68;

    int idx = blockIdx.x;
    int qt = (int)((sqrtf(8.f * idx + 1.f) - 1.f) * 0.5f);
    while ((qt + 1) * (qt + 2) / 2 <= idx) qt++;
    while (qt * (qt + 1) / 2 > idx) qt--;
    int kt = idx - qt * (qt + 1) / 2;

    int bh = blockIdx.y;
    int b = bh >> 3, h = bh & 7;
    int q0 = qt * 64, k0 = kt * 64;
    int rbase = k0 - q0 + 1856;

    int tid = threadIdx.x;
    int tx = tid & 15, ty = tid >> 4, wid = tid >> 5;

    #pragma unroll
    for (int r = 0; r < 2; r++) {
        int u = tid + r * 256;
        int row = u >> 3, c8 = (u & 7) * 8;
        size_t qoff = ((size_t)b * L_ + q0 + row) * 512 + h * 64 + c8;
        size_t koff = ((size_t)b * L_ + k0 + row) * 512 + h * 64 + c8;
        *(uint4*)(sQh + row * 72 + c8) = *(const uint4*)(g_qph + qoff);
        *(uint4*)(sQl + row * 72 + c8) = *(const uint4*)(g_qpl + qoff);
        *(uint4*)(sKh + row * 72 + c8) = *(const uint4*)(g_kph + koff);
        *(uint4*)(sKl + row * 72 + c8) = *(const uint4*)(g_kpl + koff);
    }
    uint4 z4 = make_uint4(0, 0, 0, 0);
    #pragma unroll
    for (int r = 0; r < 4; r++) {
        int u = tid + r * 256;
        int row = u >> 3, c8 = (u & 7) * 8;
        int rr = rbase + row;
        bool valid = (row < 127) && (rr >= 0) && (rr < L_);
        size_t eoff = (size_t)(rr + 1) * 512 + h * 64 + c8;
        *(uint4*)(sEh + row * 72 + c8) = valid ? *(const uint4*)(g_eh + eoff) : z4;
        *(uint4*)(sEl + row * 72 + c8) = valid ? *(const uint4*)(g_el + eoff) : z4;
    }
    __syncthreads();

    int ib = wid & 3, half = wid >> 2;
    wmma::fragment<wmma::accumulator, 16, 16, 16, float> acc[6];
    #pragma unroll
    for (int t = 0; t < 6; t++) wmma::fill_fragment(acc[t], 0.0f);

    #pragma unroll
    for (int kk = 0; kk < 4; kk++) {
        wmma::fragment<wmma::matrix_a, 16, 16, 16, __nv_bfloat16, wmma::row_major> ah, al;
        wmma::load_matrix_sync(ah, sQh + (ib*16) * 72 + kk*16, 72);
        wmma::load_matrix_sync(al, sQl + (ib*16) * 72 + kk*16, 72);
        #pragma unroll
        for (int t = 0; t < 6; t++) {
            int jb = half * 6 + t;
            const __nv_bfloat16 *ph, *pl;
            if (jb < 4) { ph = sKh + (jb*16) * 72 + kk*16; pl = sKl + (jb*16) * 72 + kk*16; }
            else        { ph = sEh + ((jb-4)*16) * 72 + kk*16; pl = sEl + ((jb-4)*16) * 72 + kk*16; }
            wmma::fragment<wmma::matrix_b, 16, 16, 16, __nv_bfloat16, wmma::col_major> bh, bl;
            wmma::load_matrix_sync(bh, ph, 72);
            wmma::load_matrix_sync(bl, pl, 72);
            wmma::mma_sync(acc[t], ah, bh, acc[t]);
            wmma::mma_sync(acc[t], ah, bl, acc[t]);
            wmma::mma_sync(acc[t], al, bh, acc[t]);
        }
    }
    __syncthreads();

    #pragma unroll
    for (int t = 0; t < 6; t++) {
        int jb = half * 6 + t;
        if (jb < 4)
            wmma::store_matrix_sync(SO + (size_t)(ib*16) * 68 + jb*16, acc[t], 68,
                                    wmma::mem_row_major);
        else
            wmma::store_matrix_sync(TO + (size_t)(ib*16) * 132 + (jb-4)*16, acc[t], 132,
                                    wmma::mem_row_major);
    }
    __syncthreads();

    bool diag = (qt == kt);
    float* out = attn + ((size_t)bh * L_ + q0) * L_ + k0;
    #pragma unroll
    for (int i = 0; i < 4; i++) {
        int row = ty * 4 + i;
        float e4[4];
        #pragma unroll
        for (int j = 0; j < 4; j++) {
            int col = tx * 4 + j;
            float v = (SO[(size_t)row * 68 + col]
                     + TO[(size_t)row * 132 + col - row + 63]) * 0.125f;
            e4[j] = (diag && col > row) ? 0.f : __expf(v);
        }
        *(float4*)(out + (size_t)row * L_ + tx*4) =
            make_float4(e4[0], e4[1], e4[2], e4[3]);
        float s = e4[0] + e4[1] + e4[2] + e4[3];
        #pragma unroll
        for (int off = 8; off > 0; off >>= 1)
            s += __shfl_xor_sync(0xffffffffu, s, off, 16);
        if (tx == 0)
            g_s[((size_t)bh * NT_ + kt) * L_ + q0 + row] = s;
    }
}

// ---------------------------------------------------------------------------
// Combine per-tile sums into per-row 1/sum.
// ---------------------------------------------------------------------------
__global__ __launch_bounds__(256)
void statcomb_kernel()
{
    int p = blockIdx.x * 256 + threadIdx.x;
    if (p >= BH_ * L_) return;
    int bh = p / L_, q = p - bh * L_;
    int nt = q / 64 + 1;

    const float* st = g_s + (size_t)bh * NT_ * L_ + q;
    float S = 0.f;
    for (int t = 0; t < nt; t++) S += st[(size_t)t * L_];
    g_I[p] = 1.f / S;
}

// ---------------------------------------------------------------------------
// WMMA av: per (qt64, bh, split) tile O_partial = P @ V.
// Reads ex from attn, p = ex*I_row (masked), writes p back (final attn),
// converts p to bf16 hi/lo, 3-term MMA vs staged Vh/Vl. Zerofill unchanged.
// ---------------------------------------------------------------------------
#define AVPH 0
#define AVPL 5120
#define AVVH 10240
#define AVVL 14848
#define AV_SMEM 19456

__global__ __launch_bounds__(256)
void av_wmma_kernel(float* __restrict__ attn)
{
    extern __shared__ char dsm[];
    __nv_bfloat16* sPh = (__nv_bfloat16*)(dsm + AVPH);   // [64][40]
    __nv_bfloat16* sPl = (__nv_bfloat16*)(dsm + AVPL);
    __nv_bfloat16* sVh = (__nv_bfloat16*)(dsm + AVVH);   // [32][72]
    __nv_bfloat16* sVl = (__nv_bfloat16*)(dsm + AVVL);
    __shared__ float sI[64];

    int qt = blockIdx.x;
    int bh = blockIdx.y;
    int s  = blockIdx.z;
    int b = bh >> 3, h = bh & 7;
    int q0 = qt * 64;
    int tid = threadIdx.x, wid = tid >> 5;

    int kbeg = s * SPLITW;
    int kend = min(q0 + 64, kbeg + SPLITW);

    float* arow = attn + ((size_t)bh * L_ + q0) * L_;

    if (kbeg < kend) {
        if (tid < 64) sI[tid] = g_I[(size_t)bh * L_ + q0 + tid];
        __syncthreads();

        int wm = wid & 3, wn = wid >> 2;
        wmma::fragment<wmma::accumulator, 16, 16, 16, float> acc[2];
        wmma::fill_fragment(acc[0], 0.0f);
        wmma::fill_fragment(acc[1], 0.0f);

        for (int k0 = kbeg; k0 < kend; k0 += 32) {   // (kend-kbeg) % 32 == 0
            // normalize + write-back + bf16-split P chunk (64 x 32)
            #pragma unroll
            for (int t = 0; t < 2; t++) {
                int u = tid + t * 256;               // 0..511
                int row = u >> 3, c4 = u & 7;
                int kb = k0 + c4 * 4;
                int qrow = q0 + row;
                float Iv = sI[row];
                float4 xv = *(float4*)(arow + (size_t)row * L_ + kb);
                float4 p;
                p.x = (kb + 0 <= qrow) ? xv.x * Iv : 0.f;
                p.y = (kb + 1 <= qrow) ? xv.y * Iv : 0.f;
                p.z = (kb + 2 <= qrow) ? xv.z * Iv : 0.f;
                p.w = (kb + 3 <= qrow) ? xv.w * Iv : 0.f;
                *(float4*)(arow + (size_t)row * L_ + kb) = p;   // final attn
                float ps[4] = {p.x, p.y, p.z, p.w};
                __nv_bfloat16 hb[4], lb[4];
                #pragma unroll
                for (int j = 0; j < 4; j++) {
                    hb[j] = __float2bfloat16(ps[j]);
                    lb[j] = __float2bfloat16(ps[j] - __bfloat162float(hb[j]));
                }
                __nv_bfloat162* dh = (__nv_bfloat162*)(sPh + row * 40 + c4 * 4);
                __nv_bfloat162* dl = (__nv_bfloat162*)(sPl + row * 40 + c4 * 4);
                dh[0] = __halves2bfloat162(hb[0], hb[1]);
                dh[1] = __halves2bfloat162(hb[2], hb[3]);
                dl[0] = __halves2bfloat162(lb[0], lb[1]);
                dl[1] = __halves2bfloat162(lb[2], lb[3]);
            }
            // stage V chunk (32 x 64) hi/lo
            {
                int r = tid >> 3, c8 = (tid & 7) * 8;
                size_t off = ((size_t)b * L_ + k0 + r) * 512 + h * 64 + c8;
                *(uint4*)(sVh + r * 72 + c8) = *(const uint4*)(g_vph + off);
                *(uint4*)(sVl + r * 72 + c8) = *(const uint4*)(g_vpl + off);
            }
            __syncthreads();

            #pragma unroll
            for (int kk = 0; kk < 2; kk++) {
                wmma::fragment<wmma::matrix_a, 16, 16, 16, __nv_bfloat16, wmma::row_major> ah, al;
                wmma::load_matrix_sync(ah, sPh + (wm*16) * 40 + kk*16, 40);
                wmma::load_matrix_sync(al, sPl + (wm*16) * 40 + kk*16, 40);
                #pragma unroll
                for (int j = 0; j < 2; j++) {
                    wmma::fragment<wmma::matrix_b, 16, 16, 16, __nv_bfloat16, wmma::row_major> bhf, blf;
                    wmma::load_matrix_sync(bhf, sVh + (kk*16) * 72 + wn*32 + j*16, 72);
                    wmma::load_matrix_sync(blf, sVl + (kk*16) * 72 + wn*32 + j*16, 72);
                    wmma::mma_sync(acc[j], ah, bhf, acc[j]);
                    wmma::mma_sync(acc[j], ah, blf, acc[j]);
                    wmma::mma_sync(acc[j], al, bhf, acc[j]);
                }
            }
            __syncthreads();
        }

        float* op = g_op + (size_t)s * (BH_*L_*DH_) + ((size_t)bh * L_ + q0) * 64;
        #pragma unroll
        for (int j = 0; j < 2; j++)
            wmma::store_matrix_sync(op + (size_t)(wm*16) * 64 + wn*32 + j*16,
                                    acc[j], 64, wmma::mem_row_major);
    }

    // zero-fill this split's strictly-non-causal columns for these 64 rows
    int zs = max(kbeg, q0 + 64) >> 2;
    int ze = min(kbeg + SPLITW, L_) >> 2;
    if (zs < ze) {
        float4 z = make_float4(0.f, 0.f, 0.f, 0.f);
        int row = tid >> 2;
        float4* rp = (float4*)(arow + (size_t)row * L_);
        for (int c4 = zs + (tid & 3); c4 < ze; c4 += 4) rp[c4] = z;
    }
}

// ---------------------------------------------------------------------------
// oproj. Tile 128x64, micro 8x4, per-64-row-half split count (verified R10).
// ---------------------------------------------------------------------------
__global__ __launch_bounds__(256)
void oproj_kernel(const float* __restrict__ Wo, const float* __restrict__ bo,
                  float* __restrict__ out)
{
    __shared__ float As[16][132];
    __shared__ float Bs[16][68];
    int tid = threadIdx.x;
    int tx = tid & 15, ty = tid >> 4;
    int m0 = blockIdx.y * 128, n0 = blockIdx.x * 64;
    int b = m0 / L_;
    int l0 = m0 - b * L_;
    float acc[8][4] = {};

    int mA = tid >> 2, gA = tid & 3;
    int kB = tid >> 4, gB = tid & 15;

    for (int k0 = 0; k0 < 512; k0 += 16) {
        int h = k0 >> 6, dh0 = k0 & 63;
        #pragma unroll
        for (int half = 0; half < 2; half++) {
            int m = half * 64 + mA;
            int nsH = (l0 + half * 64 + 64 + SPLITW - 1) / SPLITW;
            const float* base = g_op + (((size_t)(b*8 + h) * L_ + l0 + m) * 64 + dh0 + gA*4);
            float4 a4 = *(const float4*)(base);
            for (int ss = 1; ss < nsH; ss++) {
                float4 t = *(const float4*)(base + (size_t)ss * (BH_*L_*DH_));
                a4.x += t.x; a4.y += t.y; a4.z += t.z; a4.w += t.w;
            }
            As[gA*4+0][m] = a4.x; As[gA*4+1][m] = a4.y;
            As[gA*4+2][m] = a4.z; As[gA*4+3][m] = a4.w;
        }
        float4 wv = *(const float4*)(Wo + (size_t)(k0 + kB) * 512 + n0 + gB * 4);
        Bs[kB][gB*4+0] = wv.x; Bs[kB][gB*4+1] = wv.y;
        Bs[kB][gB*4+2] = wv.z; Bs[kB][gB*4+3] = wv.w;
        __syncthreads();
        #pragma unroll
        for (int kk = 0; kk < 16; kk++) {
            float a[8], bv[4];
            #pragma unroll
            for (int i = 0; i < 8; i++) a[i] = As[kk][ty * 8 + i];
            #pragma unroll
            for (int j = 0; j < 4; j++) bv[j] = Bs[kk][tx * 4 + j];
            #pragma unroll
            for (int i = 0; i < 8; i++)
                #pragma unroll
                for (int j = 0; j < 4; j++)
                    acc[i][j] += a[i] * bv[j];
        }
        __syncthreads();
    }
    float b0 = bo[n0 + tx*4 + 0], b1 = bo[n0 + tx*4 + 1];
    float b2 = bo[n0 + tx*4 + 2], b3 = bo[n0 + tx*4 + 3];
    #pragma unroll
    for (int i = 0; i < 8; i++) {
        float4 o = make_float4(acc[i][0] + b0, acc[i][1] + b1,
                               acc[i][2] + b2, acc[i][3] + b3);
        *(float4*)(out + (size_t)(m0 + ty*8 + i) * 512 + n0 + tx*4) = o;
    }
}

// ---------------------------------------------------------------------------
extern "C" void kernel_launch(void* const* d_in, const int* in_sizes, int n_in,
                              void* d_out, int out_size)
{
    const float* q  = (const float*)d_in[0];
    const float* k  = (const float*)d_in[1];
    const float* v  = (const float*)d_in[2];
    const float* Wq = (const float*)d_in[4];
    const float* bq = (const float*)d_in[5];
    const float* Wk = (const float*)d_in[6];
    const float* bk = (const float*)d_in[7];
    const float* Wv = (const float*)d_in[8];
    const float* bv = (const float*)d_in[9];
    const float* E  = (const float*)d_in[10];
    const float* Wo = (const float*)d_in[11];
    const float* bo = (const float*)d_in[12];

    float* out_ptr  = (float*)d_out;
    float* attn_ptr = out_ptr + OUT_ELEMS;   // tuple order: (out, attn)

    cudaFuncSetAttribute(qkv_wmma_kernel,
                         cudaFuncAttributeMaxDynamicSharedMemorySize, QKV_DSMEM);
    cudaFuncSetAttribute(scores_wmma_kernel,
                         cudaFuncAttributeMaxDynamicSharedMemorySize, SCW_SMEM);
    cudaFuncSetAttribute(av_wmma_kernel,
                         cudaFuncAttributeMaxDynamicSharedMemorySize, AV_SMEM);

    split_in_kernel<<<dim3(1920, 3), 256>>>(q, k, v);
    split_w_kernel<<<dim3(256, 3), 256>>>(Wq, Wk, Wv);
    split_e_kernel<<<961, 256>>>(E);
    qkv_wmma_kernel<<<dim3(8, 30, 3), 256, QKV_DSMEM>>>(bq, bk, bv);
    scores_wmma_kernel<<<dim3(465, 16), 256, SCW_SMEM>>>(attn_ptr);
    statcomb_kernel<<<(BH_ * L_ + 255) / 256, 256>>>();
    av_wmma_kernel<<<dim3(30, 16, NSPLIT), 256, AV_SMEM>>>(attn_ptr);
    oproj_kernel<<<dim3(8, 30), 256>>>(Wo, bo, out_ptr);
}